// round 13
// baseline (speedup 1.0000x reference)
#include <cuda_runtime.h>

#define N_NODES   50000
#define N_EDGES   600000
#define N_GRAPHS  256
#define W_ELL     64                                       // max in-degree slots
#define NPB       16                                       // nodes per GEMM block
#define PSTRIP    8                                        // nodes per pool strip
#define N_STRIPS  (N_NODES / PSTRIP)                       // 6250

typedef unsigned long long ull;

#define FMA_F32X2(d, a, b, c) \
    asm("fma.rn.f32x2 %0, %1, %2, %3;" : "=l"(d) : "l"(a), "l"(b), "l"(c))
#define ADD_F32X2(d, a, b) \
    asm("add.rn.f32x2 %0, %1, %2;" : "=l"(d) : "l"(a), "l"(b))

__device__ __forceinline__ ull pack2(float x, float y) {
    ull r; asm("mov.b64 %0, {%1, %2};" : "=l"(r) : "f"(x), "f"(y)); return r;
}
__device__ __forceinline__ float2 unpack2(ull v) {
    float2 r; asm("mov.b64 {%0, %1}, %2;" : "=f"(r.x), "=f"(r.y) : "l"(v)); return r;
}

// ---------------- scratch (device globals; no allocation allowed) ----------
__device__ int    g_stride;                 // 1 = int32 indices, 2 = int64 (low word)
__device__ int    g_cursor[N_NODES];        // per-dst slot cursor == in-degree
__device__ int    g_col [N_NODES * W_ELL];  // ELL src ids, node-major
__device__ float  g_dinv[N_NODES];          // dinv[n]
__device__ float  g_h1  [N_NODES * 64];     // dinv_n * relu(s_n W1 + b1)
__device__ float  g_z1  [N_NODES * 64];     // dn * (h1'[n] + sum_j h1'[src_j])
__device__ float  g_t2  [N_NODES * 64];     // dinv[n] * (relu(z1 W2 + b2) @ W3)
__device__ float  g_pool[N_GRAPHS * 64];
__device__ float  g_cntf[N_GRAPHS];

// ---------------- init: dtype detect + zero counters (fused) ----------------
__global__ void k_init(const unsigned int* __restrict__ ew) {
    int i = blockIdx.x * blockDim.x + threadIdx.x;
    if (i == 0) {
        int s = 2;
        for (int j = 1; j < 2048; j += 2)
            if (ew[j] != 0u) { s = 1; break; }
        g_stride = s;
    }
    if (i < N_NODES) g_cursor[i] = 0;
    if (i < N_GRAPHS * 64) g_pool[i] = 0.0f;
    if (i < N_GRAPHS) g_cntf[i] = 0.0f;
}

__device__ __forceinline__ int load_idx(const unsigned int* __restrict__ w, int elem) {
    return (int)w[(long long)elem * g_stride];
}

// ---------------- ELL scatter (node-major; no row pointers, no scan) -------
__global__ void k_scatter(const unsigned int* __restrict__ ei) {
    int e = blockIdx.x * blockDim.x + threadIdx.x;
    if (e < N_EDGES) {
        int s = load_idx(ei, e);
        int d = load_idx(ei, N_EDGES + e);
        int pos = atomicAdd(&g_cursor[d], 1);
        if (pos < W_ELL) g_col[d * W_ELL + pos] = s;
    }
}

// ---------------- layer 1 + h1': 8 lanes per node ---------------------------
// s = dn*(dn*x_n + sum_j dinv_sj*x_sj); lanes then write the 64 cols of
// h1'[n,c] = dn*relu(s*W1[c]+b1[c]).
__global__ void __launch_bounds__(256) k_s(const float* __restrict__ x,
                                           const float* __restrict__ W1,
                                           const float* __restrict__ b1) {
    int grp  = (blockIdx.x * 256 + threadIdx.x) >> 3;
    int lane = threadIdx.x & 7;
    if (grp >= N_NODES) return;
    int n = grp;
    int cnt = min(g_cursor[n], W_ELL);
    float part = 0.0f;
    for (int j = lane; j < cnt; j += 8) {
        int src = g_col[n * W_ELL + j];
        float dsrc = rsqrtf((float)min(g_cursor[src], W_ELL) + 1.0f);
        part = fmaf(dsrc, x[src], part);
    }
#pragma unroll
    for (int off = 4; off > 0; off >>= 1)
        part += __shfl_xor_sync(0xffffffffu, part, off);
    float dn = rsqrtf((float)cnt + 1.0f);
    float s  = dn * (part + dn * x[n]);
    if (lane == 0) g_dinv[n] = dn;
#pragma unroll
    for (int i = 0; i < 8; i++) {
        int c = i * 8 + lane;     // consecutive lanes -> consecutive cols
        g_h1[n * 64 + c] = dn * fmaxf(fmaf(s, W1[c], b1[c]), 0.0f);
    }
}

// ---------------- layer 2 aggregation: 2 nodes/warp, float4 rows -----------
// z1[n] = dn*(h1'[n] + sum_j h1'[src_j]); half-warp per node, lane owns 4
// channels (LDG.128), shfl width-16 column broadcast, packed f32x2 adds.
__global__ void __launch_bounds__(128) k_agg_l2() {
    int warp = (blockIdx.x * 128 + threadIdx.x) >> 5;
    int lane = threadIdx.x & 31;
    int half = lane >> 4, hl = lane & 15;
    int n = warp * 2 + half;                 // 25000 warps exactly
    if (n >= N_NODES) return;
    const float4* h1 = (const float4*)g_h1;
    float4 a = h1[n * 16 + hl];
    ull acc0 = pack2(a.x, a.y), acc1 = pack2(a.z, a.w);
    int cnt = min(g_cursor[n], W_ELL);
    const int* cp = g_col + n * W_ELL;
    for (int j0 = 0; j0 < cnt; j0 += 16) {
        int col = (j0 + hl < cnt) ? cp[j0 + hl] : 0;
        int m = min(cnt - j0, 16);
        int jj = 0;
        for (; jj + 3 < m; jj += 4) {
            int c0 = __shfl_sync(0xffffffffu, col, jj,     16);
            int c1 = __shfl_sync(0xffffffffu, col, jj + 1, 16);
            int c2 = __shfl_sync(0xffffffffu, col, jj + 2, 16);
            int c3 = __shfl_sync(0xffffffffu, col, jj + 3, 16);
            float4 v0 = h1[c0 * 16 + hl];
            float4 v1 = h1[c1 * 16 + hl];
            float4 v2 = h1[c2 * 16 + hl];
            float4 v3 = h1[c3 * 16 + hl];
            ADD_F32X2(acc0, acc0, pack2(v0.x, v0.y));
            ADD_F32X2(acc1, acc1, pack2(v0.z, v0.w));
            ADD_F32X2(acc0, acc0, pack2(v1.x, v1.y));
            ADD_F32X2(acc1, acc1, pack2(v1.z, v1.w));
            ADD_F32X2(acc0, acc0, pack2(v2.x, v2.y));
            ADD_F32X2(acc1, acc1, pack2(v2.z, v2.w));
            ADD_F32X2(acc0, acc0, pack2(v3.x, v3.y));
            ADD_F32X2(acc1, acc1, pack2(v3.z, v3.w));
        }
        for (; jj < m; jj++) {
            int c0 = __shfl_sync(0xffffffffu, col, jj, 16);
            float4 v = h1[c0 * 16 + hl];
            ADD_F32X2(acc0, acc0, pack2(v.x, v.y));
            ADD_F32X2(acc1, acc1, pack2(v.z, v.w));
        }
    }
    float dn = g_dinv[n];
    float2 r0 = unpack2(acc0), r1 = unpack2(acc1);
    ((float4*)g_z1)[n * 16 + hl] =
        make_float4(dn * r0.x, dn * r0.y, dn * r1.x, dn * r1.y);
}

// ---------------- fused GEMMs: t2' = dinv_n * (relu(z1 W2 + b2) @ W3) ------
__global__ void __launch_bounds__(128) k_gemm23(const float* __restrict__ W2,
                                                const float* __restrict__ b2,
                                                const float* __restrict__ W3) {
    __shared__ __align__(16) float row[64];
    __shared__ __align__(16) float h2s[128];
    __shared__ float partial[128];
    int t = threadIdx.x;
    int c = t & 63, half = t >> 6;

    ull w2p[32];
#pragma unroll
    for (int kp = 0; kp < 32; kp++)
        w2p[kp] = pack2(W2[(2 * kp) * 128 + t], W2[(2 * kp + 1) * 128 + t]);
    float b2c = b2[t];

    ull w3p[32];
#pragma unroll
    for (int kp = 0; kp < 32; kp++) {
        int k0 = half * 64 + 2 * kp;
        w3p[kp] = pack2(W3[k0 * 64 + c], W3[(k0 + 1) * 64 + c]);
    }

    int base = blockIdx.x * NPB;
    for (int ni = 0; ni < NPB; ni++) {
        int n = base + ni;
        if (t < 64) row[t] = g_z1[n * 64 + t];
        __syncthreads();

        // h2 = relu(z1 @ W2 + b2)
        ull acc2 = pack2(0.0f, 0.0f);
        const ull* rp = (const ull*)row;
#pragma unroll
        for (int kp = 0; kp < 32; kp++) FMA_F32X2(acc2, rp[kp], w2p[kp], acc2);
        float2 a2 = unpack2(acc2);
        h2s[t] = fmaxf(a2.x + a2.y + b2c, 0.0f);
        __syncthreads();

        // t2' = dinv_n * (h2 @ W3)
        ull acc3 = pack2(0.0f, 0.0f);
        const ull* hp = (const ull*)(h2s + half * 64);
#pragma unroll
        for (int kp = 0; kp < 32; kp++) FMA_F32X2(acc3, hp[kp], w3p[kp], acc3);
        float2 a3 = unpack2(acc3);
        partial[t] = a3.x + a3.y;
        __syncthreads();
        if (half == 0) {
            float dn = g_dinv[n];
            g_t2[n * 64 + c] = dn * (partial[c] + partial[c + 64]);
        }
        __syncthreads();
    }
}

// ---------------- fused layer-3 aggregation + pooling ----------------------
// half-warp per 8-node strip; lane owns 4 channels; gather is a float4
// row-sum, result relu'd and accumulated into pooled sums (batch sorted).
__global__ void __launch_bounds__(128) k_agg_pool(const float* __restrict__ b3,
                                                  const unsigned int* __restrict__ batch) {
    int warp  = (blockIdx.x * 128 + threadIdx.x) >> 5;
    int lane  = threadIdx.x & 31;
    int half  = lane >> 4, hl = lane & 15;
    int strip = warp * 2 + half;
    if (strip >= N_STRIPS) return;
    int n0 = strip * PSTRIP;
    const float4* t2 = (const float4*)g_t2;
    float b30 = b3[4 * hl], b31 = b3[4 * hl + 1];
    float b32 = b3[4 * hl + 2], b33 = b3[4 * hl + 3];
    int curg = load_idx(batch, n0);
    float p0 = 0.0f, p1 = 0.0f, p2 = 0.0f, p3 = 0.0f, cntf = 0.0f;
    for (int n = n0; n < n0 + PSTRIP; n++) {
        int g = load_idx(batch, n);
        if (g != curg) {
            atomicAdd(&g_pool[curg * 64 + 4 * hl],     p0);
            atomicAdd(&g_pool[curg * 64 + 4 * hl + 1], p1);
            atomicAdd(&g_pool[curg * 64 + 4 * hl + 2], p2);
            atomicAdd(&g_pool[curg * 64 + 4 * hl + 3], p3);
            if (hl == 0) atomicAdd(&g_cntf[curg], cntf);
            p0 = p1 = p2 = p3 = 0.0f; cntf = 0.0f; curg = g;
        }
        float4 a = t2[n * 16 + hl];
        ull a0 = pack2(a.x, a.y), a1 = pack2(a.z, a.w);
        int ecnt = min(g_cursor[n], W_ELL);
        const int* cp = g_col + n * W_ELL;
        for (int j0 = 0; j0 < ecnt; j0 += 16) {
            int col = (j0 + hl < ecnt) ? cp[j0 + hl] : 0;
            int m = min(ecnt - j0, 16);
            int jj = 0;
            for (; jj + 3 < m; jj += 4) {
                int c0 = __shfl_sync(0xffffffffu, col, jj,     16);
                int c1 = __shfl_sync(0xffffffffu, col, jj + 1, 16);
                int c2 = __shfl_sync(0xffffffffu, col, jj + 2, 16);
                int c3 = __shfl_sync(0xffffffffu, col, jj + 3, 16);
                float4 v0 = t2[c0 * 16 + hl];
                float4 v1 = t2[c1 * 16 + hl];
                float4 v2 = t2[c2 * 16 + hl];
                float4 v3 = t2[c3 * 16 + hl];
                ADD_F32X2(a0, a0, pack2(v0.x, v0.y));
                ADD_F32X2(a1, a1, pack2(v0.z, v0.w));
                ADD_F32X2(a0, a0, pack2(v1.x, v1.y));
                ADD_F32X2(a1, a1, pack2(v1.z, v1.w));
                ADD_F32X2(a0, a0, pack2(v2.x, v2.y));
                ADD_F32X2(a1, a1, pack2(v2.z, v2.w));
                ADD_F32X2(a0, a0, pack2(v3.x, v3.y));
                ADD_F32X2(a1, a1, pack2(v3.z, v3.w));
            }
            for (; jj < m; jj++) {
                int c0 = __shfl_sync(0xffffffffu, col, jj, 16);
                float4 v = t2[c0 * 16 + hl];
                ADD_F32X2(a0, a0, pack2(v.x, v.y));
                ADD_F32X2(a1, a1, pack2(v.z, v.w));
            }
        }
        float dn = g_dinv[n];
        float2 u0 = unpack2(a0), u1 = unpack2(a1);
        p0 += fmaxf(fmaf(dn, u0.x, b30), 0.0f);
        p1 += fmaxf(fmaf(dn, u0.y, b31), 0.0f);
        p2 += fmaxf(fmaf(dn, u1.x, b32), 0.0f);
        p3 += fmaxf(fmaf(dn, u1.y, b33), 0.0f);
        cntf += 1.0f;
    }
    atomicAdd(&g_pool[curg * 64 + 4 * hl],     p0);
    atomicAdd(&g_pool[curg * 64 + 4 * hl + 1], p1);
    atomicAdd(&g_pool[curg * 64 + 4 * hl + 2], p2);
    atomicAdd(&g_pool[curg * 64 + 4 * hl + 3], p3);
    if (hl == 0) atomicAdd(&g_cntf[curg], cntf);
}

// ---------------- head ----------------
__global__ void k_head(const float* __restrict__ l1w, const float* __restrict__ l1b,
                       const float* __restrict__ l2w, const float* __restrict__ l2b,
                       float* __restrict__ out) {
    int g = blockIdx.x * blockDim.x + threadIdx.x;
    if (g >= N_GRAPHS) return;
    float inv = 1.0f / fmaxf(g_cntf[g], 1.0f);
    float p[64];
#pragma unroll
    for (int k = 0; k < 64; k++) p[k] = g_pool[g * 64 + k] * inv;
    float o = l2b[0];
#pragma unroll 4
    for (int j = 0; j < 32; j++) {
        float z = l1b[j];
#pragma unroll
        for (int k = 0; k < 64; k++) z = fmaf(p[k], l1w[k * 32 + j], z);
        o = fmaf(fmaxf(z, 0.0f), l2w[j], o);
    }
    out[g] = o;
}

// ---------------- launch ----------------
extern "C" void kernel_launch(void* const* d_in, const int* in_sizes, int n_in,
                              void* d_out, int out_size) {
    const float* x   = (const float*)d_in[0];
    const float* W1  = (const float*)d_in[1];
    const float* b1  = (const float*)d_in[2];
    const float* W2  = (const float*)d_in[3];
    const float* b2  = (const float*)d_in[4];
    const float* W3  = (const float*)d_in[5];
    const float* b3  = (const float*)d_in[6];
    const float* l1w = (const float*)d_in[7];
    const float* l1b = (const float*)d_in[8];
    const float* l2w = (const float*)d_in[9];
    const float* l2b = (const float*)d_in[10];
    const unsigned int* ei    = (const unsigned int*)d_in[11];
    const unsigned int* batch = (const unsigned int*)d_in[12];
    float* out = (float*)d_out;

    const int TB = 256;
    const int gN = (N_NODES + TB - 1) / TB;
    const int gE = (N_EDGES + TB - 1) / TB;
    const int gS = (N_NODES * 8 + TB - 1) / TB;    // 8 lanes per node

    k_init   <<<gN, TB>>>(ei);
    k_scatter<<<gE, TB>>>(ei);
    k_s      <<<gS, TB>>>(x, W1, b1);

    // 2-nodes-per-warp float4 row-sum gathers around the fused GEMMs
    k_agg_l2  <<<(N_NODES / 2 * 32 + 127) / 128, 128>>>();
    k_gemm23  <<<N_NODES / NPB, 128>>>(W2, b2, W3);
    k_agg_pool<<<(N_STRIPS / 2 * 32 + 127) / 128, 128>>>(b3, batch);

    k_head<<<1, N_GRAPHS>>>(l1w, l1b, l2w, l2b, out);
}

// round 14
// speedup vs baseline: 1.1537x; 1.1537x over previous
#include <cuda_runtime.h>

#define N_NODES   50000
#define N_EDGES   600000
#define N_GRAPHS  256
#define W_ELL     64                                       // max in-degree slots
#define NPB       16                                       // nodes per GEMM block
#define PSTRIP    8                                        // nodes per pool strip
#define N_STRIPS  (N_NODES / PSTRIP)                       // 6250

typedef unsigned long long ull;

#define FMA_F32X2(d, a, b, c) \
    asm("fma.rn.f32x2 %0, %1, %2, %3;" : "=l"(d) : "l"(a), "l"(b), "l"(c))

__device__ __forceinline__ ull pack2(float x, float y) {
    ull r; asm("mov.b64 %0, {%1, %2};" : "=l"(r) : "f"(x), "f"(y)); return r;
}
__device__ __forceinline__ float2 unpack2(ull v) {
    float2 r; asm("mov.b64 {%0, %1}, %2;" : "=f"(r.x), "=f"(r.y) : "l"(v)); return r;
}

// ---------------- scratch (device globals; no allocation allowed) ----------
__device__ int    g_stride;                 // 1 = int32 indices, 2 = int64 (low word)
__device__ int    g_cursor[N_NODES];        // per-dst slot cursor == in-degree
__device__ int    g_col [N_NODES * W_ELL];  // ELL src ids, node-major
__device__ float  g_dinv[N_NODES];          // dinv[n]
__device__ float  g_h1  [N_NODES * 64];     // dinv_n * relu(s_n W1 + b1)
__device__ float  g_z1  [N_NODES * 64];     // dn * (h1'[n] + sum_j h1'[src_j])
__device__ float  g_t2  [N_NODES * 64];     // dinv[n] * (relu(z1 W2 + b2) @ W3)
__device__ float  g_pool[N_GRAPHS * 64];
__device__ float  g_cntf[N_GRAPHS];

// ---------------- init: dtype detect + zero counters (fused) ----------------
__global__ void k_init(const unsigned int* __restrict__ ew) {
    int i = blockIdx.x * blockDim.x + threadIdx.x;
    if (i == 0) {
        int s = 2;
        for (int j = 1; j < 2048; j += 2)
            if (ew[j] != 0u) { s = 1; break; }
        g_stride = s;
    }
    if (i < N_NODES) g_cursor[i] = 0;
    if (i < N_GRAPHS * 64) g_pool[i] = 0.0f;
    if (i < N_GRAPHS) g_cntf[i] = 0.0f;
}

__device__ __forceinline__ int load_idx(const unsigned int* __restrict__ w, int elem) {
    return (int)w[(long long)elem * g_stride];
}

// ---------------- ELL scatter (node-major; no row pointers, no scan) -------
__global__ void k_scatter(const unsigned int* __restrict__ ei) {
    int e = blockIdx.x * blockDim.x + threadIdx.x;
    if (e < N_EDGES) {
        int s = load_idx(ei, e);
        int d = load_idx(ei, N_EDGES + e);
        int pos = atomicAdd(&g_cursor[d], 1);
        if (pos < W_ELL) g_col[d * W_ELL + pos] = s;
    }
}

// ---------------- layer 1 + h1': 8 lanes per node ---------------------------
// s = dn*(dn*x_n + sum_j dinv_sj*x_sj); lanes then write the 64 cols of
// h1'[n,c] = dn*relu(s*W1[c]+b1[c]).
__global__ void __launch_bounds__(256) k_s(const float* __restrict__ x,
                                           const float* __restrict__ W1,
                                           const float* __restrict__ b1) {
    int grp  = (blockIdx.x * 256 + threadIdx.x) >> 3;
    int lane = threadIdx.x & 7;
    if (grp >= N_NODES) return;
    int n = grp;
    int cnt = min(g_cursor[n], W_ELL);
    float part = 0.0f;
    for (int j = lane; j < cnt; j += 8) {
        int src = g_col[n * W_ELL + j];
        float dsrc = rsqrtf((float)min(g_cursor[src], W_ELL) + 1.0f);
        part = fmaf(dsrc, x[src], part);
    }
#pragma unroll
    for (int off = 4; off > 0; off >>= 1)
        part += __shfl_xor_sync(0xffffffffu, part, off);
    float dn = rsqrtf((float)cnt + 1.0f);
    float s  = dn * (part + dn * x[n]);
    if (lane == 0) g_dinv[n] = dn;
#pragma unroll
    for (int i = 0; i < 8; i++) {
        int c = i * 8 + lane;     // consecutive lanes -> consecutive cols
        g_h1[n * 64 + c] = dn * fmaxf(fmaf(s, W1[c], b1[c]), 0.0f);
    }
}

// ---------------- layer 2 aggregation: warp-per-node float2 row-sum --------
// z1[n] = dn * (h1'[n] + sum_j h1'[src_j]); lane owns channels {2l, 2l+1}.
// Columns loaded coalesced once per 32 edges, broadcast by shfl.
__global__ void __launch_bounds__(128) k_agg_l2() {
    int n    = (blockIdx.x * 128 + threadIdx.x) >> 5;
    int lane = threadIdx.x & 31;
    if (n >= N_NODES) return;
    const float2* h1 = (const float2*)g_h1;
    float2 acc = h1[n * 32 + lane];
    int cnt = min(g_cursor[n], W_ELL);
    const int* cp = g_col + n * W_ELL;
    for (int j0 = 0; j0 < cnt; j0 += 32) {
        int col = (j0 + lane < cnt) ? cp[j0 + lane] : 0;
        int m = min(cnt - j0, 32);
        int jj = 0;
        for (; jj + 3 < m; jj += 4) {
            int c0 = __shfl_sync(0xffffffffu, col, jj);
            int c1 = __shfl_sync(0xffffffffu, col, jj + 1);
            int c2 = __shfl_sync(0xffffffffu, col, jj + 2);
            int c3 = __shfl_sync(0xffffffffu, col, jj + 3);
            float2 v0 = h1[c0 * 32 + lane];
            float2 v1 = h1[c1 * 32 + lane];
            float2 v2 = h1[c2 * 32 + lane];
            float2 v3 = h1[c3 * 32 + lane];
            acc.x += (v0.x + v1.x) + (v2.x + v3.x);
            acc.y += (v0.y + v1.y) + (v2.y + v3.y);
        }
        for (; jj < m; jj++) {
            int c0 = __shfl_sync(0xffffffffu, col, jj);
            float2 v = h1[c0 * 32 + lane];
            acc.x += v.x; acc.y += v.y;
        }
    }
    float dn = g_dinv[n];
    ((float2*)g_z1)[n * 32 + lane] = make_float2(dn * acc.x, dn * acc.y);
}

// ---------------- fused GEMMs: t2' = dinv_n * (relu(z1 W2 + b2) @ W3) ------
__global__ void __launch_bounds__(128) k_gemm23(const float* __restrict__ W2,
                                                const float* __restrict__ b2,
                                                const float* __restrict__ W3) {
    __shared__ __align__(16) float row[64];
    __shared__ __align__(16) float h2s[128];
    __shared__ float partial[128];
    int t = threadIdx.x;
    int c = t & 63, half = t >> 6;

    ull w2p[32];
#pragma unroll
    for (int kp = 0; kp < 32; kp++)
        w2p[kp] = pack2(W2[(2 * kp) * 128 + t], W2[(2 * kp + 1) * 128 + t]);
    float b2c = b2[t];

    ull w3p[32];
#pragma unroll
    for (int kp = 0; kp < 32; kp++) {
        int k0 = half * 64 + 2 * kp;
        w3p[kp] = pack2(W3[k0 * 64 + c], W3[(k0 + 1) * 64 + c]);
    }

    int base = blockIdx.x * NPB;
    for (int ni = 0; ni < NPB; ni++) {
        int n = base + ni;
        if (t < 64) row[t] = g_z1[n * 64 + t];
        __syncthreads();

        // h2 = relu(z1 @ W2 + b2)
        ull acc2 = pack2(0.0f, 0.0f);
        const ull* rp = (const ull*)row;
#pragma unroll
        for (int kp = 0; kp < 32; kp++) FMA_F32X2(acc2, rp[kp], w2p[kp], acc2);
        float2 a2 = unpack2(acc2);
        h2s[t] = fmaxf(a2.x + a2.y + b2c, 0.0f);
        __syncthreads();

        // t2' = dinv_n * (h2 @ W3)
        ull acc3 = pack2(0.0f, 0.0f);
        const ull* hp = (const ull*)(h2s + half * 64);
#pragma unroll
        for (int kp = 0; kp < 32; kp++) FMA_F32X2(acc3, hp[kp], w3p[kp], acc3);
        float2 a3 = unpack2(acc3);
        partial[t] = a3.x + a3.y;
        __syncthreads();
        if (half == 0) {
            float dn = g_dinv[n];
            g_t2[n * 64 + c] = dn * (partial[c] + partial[c + 64]);
        }
        __syncthreads();
    }
}

// ---------------- fused layer-3 aggregation + pooling (warp per strip) -----
// h3[n] = relu(dn*(t2'[n] + sum_j t2'[src_j]) + b3) accumulated straight
// into pooled sums; lane owns channels {2l, 2l+1}.
__global__ void __launch_bounds__(128) k_agg_pool(const float* __restrict__ b3,
                                                  const unsigned int* __restrict__ batch) {
    int strip = (blockIdx.x * 128 + threadIdx.x) >> 5;
    int lane  = threadIdx.x & 31;
    if (strip >= N_STRIPS) return;
    int n0 = strip * PSTRIP;
    const float2* t2 = (const float2*)g_t2;
    float b3x = b3[2 * lane], b3y = b3[2 * lane + 1];
    int curg = load_idx(batch, n0);
    float2 acc = make_float2(0.0f, 0.0f);
    float cntf = 0.0f;
    for (int n = n0; n < n0 + PSTRIP; n++) {
        int g = load_idx(batch, n);
        if (g != curg) {
            atomicAdd(&g_pool[curg * 64 + 2 * lane], acc.x);
            atomicAdd(&g_pool[curg * 64 + 2 * lane + 1], acc.y);
            if (lane == 0) atomicAdd(&g_cntf[curg], cntf);
            acc = make_float2(0.0f, 0.0f); cntf = 0.0f; curg = g;
        }
        float2 a = t2[n * 32 + lane];
        int ecnt = min(g_cursor[n], W_ELL);
        const int* cp = g_col + n * W_ELL;
        for (int j0 = 0; j0 < ecnt; j0 += 32) {
            int col = (j0 + lane < ecnt) ? cp[j0 + lane] : 0;
            int m = min(ecnt - j0, 32);
            int jj = 0;
            for (; jj + 3 < m; jj += 4) {
                int c0 = __shfl_sync(0xffffffffu, col, jj);
                int c1 = __shfl_sync(0xffffffffu, col, jj + 1);
                int c2 = __shfl_sync(0xffffffffu, col, jj + 2);
                int c3 = __shfl_sync(0xffffffffu, col, jj + 3);
                float2 v0 = t2[c0 * 32 + lane];
                float2 v1 = t2[c1 * 32 + lane];
                float2 v2 = t2[c2 * 32 + lane];
                float2 v3 = t2[c3 * 32 + lane];
                a.x += (v0.x + v1.x) + (v2.x + v3.x);
                a.y += (v0.y + v1.y) + (v2.y + v3.y);
            }
            for (; jj < m; jj++) {
                int c0 = __shfl_sync(0xffffffffu, col, jj);
                float2 v = t2[c0 * 32 + lane];
                a.x += v.x; a.y += v.y;
            }
        }
        float dn = g_dinv[n];
        acc.x += fmaxf(fmaf(dn, a.x, b3x), 0.0f);
        acc.y += fmaxf(fmaf(dn, a.y, b3y), 0.0f);
        cntf += 1.0f;
    }
    atomicAdd(&g_pool[curg * 64 + 2 * lane], acc.x);
    atomicAdd(&g_pool[curg * 64 + 2 * lane + 1], acc.y);
    if (lane == 0) atomicAdd(&g_cntf[curg], cntf);
}

// ---------------- head ----------------
__global__ void k_head(const float* __restrict__ l1w, const float* __restrict__ l1b,
                       const float* __restrict__ l2w, const float* __restrict__ l2b,
                       float* __restrict__ out) {
    int g = blockIdx.x * blockDim.x + threadIdx.x;
    if (g >= N_GRAPHS) return;
    float inv = 1.0f / fmaxf(g_cntf[g], 1.0f);
    float p[64];
#pragma unroll
    for (int k = 0; k < 64; k++) p[k] = g_pool[g * 64 + k] * inv;
    float o = l2b[0];
#pragma unroll 4
    for (int j = 0; j < 32; j++) {
        float z = l1b[j];
#pragma unroll
        for (int k = 0; k < 64; k++) z = fmaf(p[k], l1w[k * 32 + j], z);
        o = fmaf(fmaxf(z, 0.0f), l2w[j], o);
    }
    out[g] = o;
}

// ---------------- launch ----------------
extern "C" void kernel_launch(void* const* d_in, const int* in_sizes, int n_in,
                              void* d_out, int out_size) {
    const float* x   = (const float*)d_in[0];
    const float* W1  = (const float*)d_in[1];
    const float* b1  = (const float*)d_in[2];
    const float* W2  = (const float*)d_in[3];
    const float* b2  = (const float*)d_in[4];
    const float* W3  = (const float*)d_in[5];
    const float* b3  = (const float*)d_in[6];
    const float* l1w = (const float*)d_in[7];
    const float* l1b = (const float*)d_in[8];
    const float* l2w = (const float*)d_in[9];
    const float* l2b = (const float*)d_in[10];
    const unsigned int* ei    = (const unsigned int*)d_in[11];
    const unsigned int* batch = (const unsigned int*)d_in[12];
    float* out = (float*)d_out;

    const int TB = 256;
    const int gN = (N_NODES + TB - 1) / TB;
    const int gE = (N_EDGES + TB - 1) / TB;
    const int gS = (N_NODES * 8 + TB - 1) / TB;    // 8 lanes per node

    k_init   <<<gN, TB>>>(ei);
    k_scatter<<<gE, TB>>>(ei);
    k_s      <<<gS, TB>>>(x, W1, b1);

    // warp-per-node float2 row-sum gathers around the fused GEMMs
    k_agg_l2  <<<(N_NODES * 32 + 127) / 128, 128>>>();
    k_gemm23  <<<N_NODES / NPB, 128>>>(W2, b2, W3);
    k_agg_pool<<<(N_STRIPS * 32 + 127) / 128, 128>>>(b3, batch);

    k_head<<<1, N_GRAPHS>>>(l1w, l1b, l2w, l2b, out);
}